// round 1
// baseline (speedup 1.0000x reference)
#include <cuda_runtime.h>
#include <math.h>

#define BATCH 8
#define SEQ   1024
#define DM    256
#define DI    512
#define NH    8
#define HD    64
#define NS    64
#define CDIM  640
#define DIP   1160
#define NTOK  (BATCH*SEQ)   // 8192

// ---------------- device scratch (no allocations allowed) ----------------
__device__ float g_x[NTOK*DM];        // residual stream
__device__ float g_zx[NTOK*DIP];      // in_proj output (z | xBC | dt_raw)
__device__ float g_xbc[NTOK*CDIM];    // silu(conv(xBC))
__device__ float g_dt[NTOK*NH];
__device__ float g_dA[NTOK*NH];
__device__ float g_ys[NTOK*DI];       // scan output
__device__ float g_y[NTOK*DI];        // gated + rmsnormed
__device__ float g_lut[8*DIP];        // layer-0 in_proj lookup (8 vocab rows)
__device__ float g_psum[BATCH*16*DM];
__device__ float g_pmax[BATCH*16*DM];
__device__ float g_pooled[BATCH*DM];

// ---------------- helpers ----------------
__device__ __forceinline__ float siluf(float x) { return x / (1.f + expf(-x)); }
__device__ __forceinline__ float geluf(float x) { return 0.5f * x * (1.f + erff(x * 0.7071067811865476f)); }

// ---------------- embedding gather ----------------
__global__ void k_embed(const int* __restrict__ ids, const float* __restrict__ emb) {
    int bt = blockIdx.x;
    int d  = threadIdx.x;
    g_x[(size_t)bt*DM + d] = emb[(size_t)ids[bt]*DM + d];
}

// ---------------- layer-0 in_proj LUT: lut[v][e] = sum_d emb[v,d] * W[e,d] ----------------
__global__ void k_lut(const float* __restrict__ emb, const float* __restrict__ W) {
    __shared__ float se[8*DM];
    for (int i = threadIdx.x; i < 8*DM; i += blockDim.x) se[i] = emb[i];
    __syncthreads();
    int e = blockIdx.x*blockDim.x + threadIdx.x;
    if (e >= DIP) return;
    float acc[8] = {0.f,0.f,0.f,0.f,0.f,0.f,0.f,0.f};
    const float* wr = W + (size_t)e*DM;
    for (int d = 0; d < DM; d++) {
        float wv = wr[d];
        #pragma unroll
        for (int v = 0; v < 8; v++) acc[v] += wv * se[v*DM + d];
    }
    #pragma unroll
    for (int v = 0; v < 8; v++) g_lut[(size_t)v*DIP + e] = acc[v];
}

// ---------------- layer-0 zxbcdt gather (rows are LUT rows) ----------------
__global__ void k_gather(const int* __restrict__ ids) {
    int bt = blockIdx.x;
    const float4* src = (const float4*)(g_lut + (size_t)ids[bt]*DIP);
    float4* dst = (float4*)(g_zx + (size_t)bt*DIP);
    for (int i = threadIdx.x; i < DIP/4; i += blockDim.x) dst[i] = src[i];
}

// ---------------- conv4 + silu + softplus(dt) + dA ----------------
__global__ void k_conv(const float* __restrict__ cw, const float* __restrict__ cb,
                       const float* __restrict__ dtb, const float* __restrict__ Alog) {
    int bt = blockIdx.x;
    int t  = bt & (SEQ-1);
    for (int c = threadIdx.x; c < CDIM; c += blockDim.x) {
        float acc = cb[c];
        #pragma unroll
        for (int k = 0; k < 4; k++) {
            int tt = t - 3 + k;
            if (tt >= 0) acc += g_zx[(size_t)(bt - 3 + k)*DIP + DI + c] * cw[c*4 + k];
        }
        g_xbc[(size_t)bt*CDIM + c] = siluf(acc);
    }
    if (threadIdx.x < NH) {
        int h = threadIdx.x;
        float xr  = g_zx[(size_t)bt*DIP + DI + CDIM + h] + dtb[h];
        float dtv = (xr > 20.f) ? xr : log1pf(expf(xr));
        g_dt[bt*NH + h] = dtv;
        g_dA[bt*NH + h] = expf(dtv * (-expf(Alog[h])));
    }
}

// ---------------- SSD scan: one block per (b,h); 256 thr = 64 p x 4 n-quarters ----------------
__global__ void k_scan(const float* __restrict__ Dp) {
    int h = blockIdx.x, b = blockIdx.y;
    int tid = threadIdx.x;
    int p = tid >> 2, q = tid & 3;
    float Dh = Dp[h];
    float hreg[16];
    #pragma unroll
    for (int i = 0; i < 16; i++) hreg[i] = 0.f;

    __shared__ float sx[16][64], sB[16][64], sC[16][64];
    __shared__ float sdt[16], sdA[16];

    for (int t0 = 0; t0 < SEQ; t0 += 16) {
        for (int i = tid; i < 16*64; i += 256) {
            int s = i >> 6, j = i & 63;
            const float* row = g_xbc + (size_t)(b*SEQ + t0 + s)*CDIM;
            sx[s][j] = row[h*HD + j];
            sB[s][j] = row[DI + j];
            sC[s][j] = row[DI + NS + j];
        }
        if (tid < 16) {
            sdt[tid] = g_dt[(b*SEQ + t0 + tid)*NH + h];
            sdA[tid] = g_dA[(b*SEQ + t0 + tid)*NH + h];
        }
        __syncthreads();
        #pragma unroll 4
        for (int s = 0; s < 16; s++) {
            float da  = sdA[s];
            float xv  = sx[s][p];
            float dtx = sdt[s] * xv;
            float y = 0.f;
            #pragma unroll
            for (int i = 0; i < 16; i++) {
                int n = q + 4*i;            // conflict-free: 4 consecutive addrs, 8-way broadcast
                hreg[i] = hreg[i]*da + dtx*sB[s][n];
                y += hreg[i]*sC[s][n];
            }
            y += __shfl_xor_sync(0xffffffffu, y, 1);
            y += __shfl_xor_sync(0xffffffffu, y, 2);
            if (q == 0)
                g_ys[(size_t)(b*SEQ + t0 + s)*DI + h*HD + p] = y + xv*Dh;
        }
        __syncthreads();
    }
}

// ---------------- gate (y * silu(z)) + RMSNorm * norm_w ----------------
__global__ void k_gate(const float* __restrict__ nw) {
    int bt = blockIdx.x, tid = threadIdx.x;
    const float* ysr = g_ys + (size_t)bt*DI;
    const float* zr  = g_zx + (size_t)bt*DIP;
    float v0 = ysr[tid]       * siluf(zr[tid]);
    float v1 = ysr[tid + 256] * siluf(zr[tid + 256]);
    __shared__ float red[256];
    red[tid] = v0*v0 + v1*v1;
    __syncthreads();
    for (int s = 128; s > 0; s >>= 1) {
        if (tid < s) red[tid] += red[tid + s];
        __syncthreads();
    }
    float scale = rsqrtf(red[0] * (1.f/DI) + 1e-5f);
    g_y[(size_t)bt*DI + tid]       = v0*scale*nw[tid];
    g_y[(size_t)bt*DI + tid + 256] = v1*scale*nw[tid + 256];
}

// ---------------- SGEMM (NT): C[m,n] = sum_k A[m,k]*W[n,k] (+R[m,n]) ----------------
// 64x64 tile, BK=16, 256 threads, 4x4 microtile per thread.
template<bool RESID>
__global__ void k_sgemm(const float* __restrict__ A, const float* __restrict__ W,
                        const float* __restrict__ R, float* __restrict__ C,
                        int N, int K) {
    __shared__ float As[16][68];
    __shared__ float Ws[16][68];
    int tid = threadIdx.x;
    int tx = tid & 15, ty = tid >> 4;
    int m0 = blockIdx.y * 64, n0 = blockIdx.x * 64;
    int lr = tid >> 2;           // row within tile (0..63)
    int lk = (tid & 3) * 4;      // k offset (0,4,8,12)

    float acc[4][4];
    #pragma unroll
    for (int i = 0; i < 4; i++)
        #pragma unroll
        for (int j = 0; j < 4; j++) acc[i][j] = 0.f;

    for (int k0 = 0; k0 < K; k0 += 16) {
        float4 av = *(const float4*)(A + (size_t)(m0 + lr)*K + k0 + lk);
        float4 wv = make_float4(0.f,0.f,0.f,0.f);
        if (n0 + lr < N) wv = *(const float4*)(W + (size_t)(n0 + lr)*K + k0 + lk);
        As[lk+0][lr] = av.x; As[lk+1][lr] = av.y; As[lk+2][lr] = av.z; As[lk+3][lr] = av.w;
        Ws[lk+0][lr] = wv.x; Ws[lk+1][lr] = wv.y; Ws[lk+2][lr] = wv.z; Ws[lk+3][lr] = wv.w;
        __syncthreads();
        #pragma unroll
        for (int kk = 0; kk < 16; kk++) {
            float4 a = *(const float4*)&As[kk][ty*4];
            float4 bv = *(const float4*)&Ws[kk][tx*4];
            float aa[4] = {a.x, a.y, a.z, a.w};
            float bb[4] = {bv.x, bv.y, bv.z, bv.w};
            #pragma unroll
            for (int i = 0; i < 4; i++)
                #pragma unroll
                for (int j = 0; j < 4; j++) acc[i][j] += aa[i]*bb[j];
        }
        __syncthreads();
    }
    #pragma unroll
    for (int i = 0; i < 4; i++) {
        int m = m0 + ty*4 + i;
        #pragma unroll
        for (int j = 0; j < 4; j++) {
            int n = n0 + tx*4 + j;
            if (n < N) {
                float v = acc[i][j];
                if (RESID) v += R[(size_t)m*N + n];
                C[(size_t)m*N + n] = v;
            }
        }
    }
}

// ---------------- pooling: (mean + max) / 2 over L ----------------
__global__ void k_pool1() {
    int seg = blockIdx.x, b = blockIdx.y, d = threadIdx.x;
    float sum = 0.f, mx = -INFINITY;
    for (int i = 0; i < 64; i++) {
        float v = g_x[(size_t)(b*SEQ + seg*64 + i)*DM + d];
        sum += v; mx = fmaxf(mx, v);
    }
    g_psum[(b*16 + seg)*DM + d] = sum;
    g_pmax[(b*16 + seg)*DM + d] = mx;
}
__global__ void k_pool2() {
    int b = blockIdx.x, d = threadIdx.x;
    float sum = 0.f, mx = -INFINITY;
    for (int s = 0; s < 16; s++) {
        sum += g_psum[(b*16 + s)*DM + d];
        mx = fmaxf(mx, g_pmax[(b*16 + s)*DM + d]);
    }
    g_pooled[b*DM + d] = (sum*(1.f/SEQ) + mx)*0.5f;
}

// ---------------- classification head ----------------
__global__ void k_head(const float* __restrict__ pw, const float* __restrict__ pb,
                       const float* __restrict__ c1w, const float* __restrict__ c1b,
                       const float* __restrict__ c2w, const float* __restrict__ c2b,
                       float* __restrict__ out) {
    int b = blockIdx.x, tid = threadIdx.x;
    __shared__ float sp[DM], s1[DM], s2[128];
    sp[tid] = g_pooled[b*DM + tid];
    __syncthreads();
    {
        float acc = pb[tid];
        const float* wr = pw + (size_t)tid*DM;
        for (int d = 0; d < DM; d++) acc += sp[d]*wr[d];
        s1[tid] = geluf(acc);
    }
    __syncthreads();
    if (tid < 128) {
        float acc = c1b[tid];
        const float* wr = c1w + (size_t)tid*DM;
        for (int d = 0; d < DM; d++) acc += s1[d]*wr[d];
        s2[tid] = geluf(acc);
    }
    __syncthreads();
    if (tid < 2) {
        float acc = c2b[tid];
        const float* wr = c2w + tid*128;
        for (int d = 0; d < 128; d++) acc += s2[d]*wr[d];
        out[b*2 + tid] = acc;
    }
}

// ---------------- launch ----------------
extern "C" void kernel_launch(void* const* d_in, const int* in_sizes, int n_in,
                              void* d_out, int out_size) {
    const int*   ids  = (const int*)  d_in[0];
    const float* emb  = (const float*)d_in[1];
    const float* inw  = (const float*)d_in[2];
    const float* cw   = (const float*)d_in[3];
    const float* cb   = (const float*)d_in[4];
    const float* dtb  = (const float*)d_in[5];
    const float* alog = (const float*)d_in[6];
    const float* Dv   = (const float*)d_in[7];
    const float* nw   = (const float*)d_in[8];
    const float* ow   = (const float*)d_in[9];
    const float* pw   = (const float*)d_in[10];
    const float* pb   = (const float*)d_in[11];
    const float* c1w  = (const float*)d_in[12];
    const float* c1b  = (const float*)d_in[13];
    const float* c2w  = (const float*)d_in[14];
    const float* c2b  = (const float*)d_in[15];
    float* out = (float*)d_out;

    float *px, *pzx, *py;
    cudaGetSymbolAddress((void**)&px,  g_x);
    cudaGetSymbolAddress((void**)&pzx, g_zx);
    cudaGetSymbolAddress((void**)&py,  g_y);

    k_embed<<<NTOK, DM>>>(ids, emb);
    for (int layer = 0; layer < 2; layer++) {
        if (layer == 0) {
            k_lut<<<(DIP + 255)/256, 256>>>(emb, inw);
            k_gather<<<NTOK, 256>>>(ids);
        } else {
            k_sgemm<false><<<dim3((DIP + 63)/64, NTOK/64), 256>>>(
                px, inw + (size_t)DIP*DM, nullptr, pzx, DIP, DM);
        }
        k_conv<<<NTOK, 256>>>(cw + (size_t)layer*CDIM*4, cb + layer*CDIM,
                              dtb + layer*NH, alog + layer*NH);
        k_scan<<<dim3(NH, BATCH), 256>>>(Dv + layer*NH);
        k_gate<<<NTOK, 256>>>(nw + layer*DI);
        k_sgemm<true><<<dim3(DM/64, NTOK/64), 256>>>(
            py, ow + (size_t)layer*DM*DI, px, px, DM, DI);
    }
    k_pool1<<<dim3(16, BATCH), DM>>>();
    k_pool2<<<BATCH, DM>>>();
    k_head<<<BATCH, DM>>>(pw, pb, c1w, c1b, c2w, c2b, out);
}

// round 3
// speedup vs baseline: 1.1037x; 1.1037x over previous
#include <cuda_runtime.h>
#include <cuda_bf16.h>
#include <cstdint>
#include <math.h>

#define BATCH 8
#define SEQ   1024
#define DM    256
#define DI    512
#define NH    8
#define HD    64
#define NS    64
#define CDIM  640
#define DIP   1160
#define NTOK  (BATCH*SEQ)   // 8192
#define NPAD_IN 1216        // 19*64

// ---------------- device scratch (no allocations allowed) ----------------
__device__ float g_x[NTOK*DM];        // residual stream
__device__ float g_zx[NTOK*DIP];      // in_proj output (z | xBC | dt_raw)
__device__ float g_xbc[NTOK*CDIM];    // silu(conv(xBC))
__device__ float g_dt[NTOK*NH];
__device__ float g_dA[NTOK*NH];
__device__ float g_ys[NTOK*DI];       // scan output
__device__ float g_lut[8*DIP];        // layer-0 in_proj lookup (8 vocab rows)
__device__ float g_psum[BATCH*16*DM];
__device__ float g_pmax[BATCH*16*DM];
__device__ float g_pooled[BATCH*DM];
// split-bf16 GEMM operands
__device__ __align__(16) __nv_bfloat16 g_a3[NTOK*3*DI];     // gate output triple [Ah|Ah|Al], K'=1536
__device__ __align__(16) __nv_bfloat16 g_x3[NTOK*3*DM];     // residual triple, K'=768
__device__ __align__(16) __nv_bfloat16 g_w3a[NPAD_IN*3*DM]; // in_proj weight triple
__device__ __align__(16) __nv_bfloat16 g_w3b[DM*3*DI];      // out_proj weight triple

// ---------------- helpers ----------------
__device__ __forceinline__ float siluf(float x) { return x / (1.f + expf(-x)); }
__device__ __forceinline__ float geluf(float x) { return 0.5f * x * (1.f + erff(x * 0.7071067811865476f)); }

// ---------------- embedding gather ----------------
__global__ void k_embed(const int* __restrict__ ids, const float* __restrict__ emb) {
    int bt = blockIdx.x;
    int d  = threadIdx.x;
    g_x[(size_t)bt*DM + d] = emb[(size_t)ids[bt]*DM + d];
}

// ---------------- layer-0 in_proj LUT ----------------
__global__ void k_lut(const float* __restrict__ emb, const float* __restrict__ W) {
    __shared__ float se[8*DM];
    for (int i = threadIdx.x; i < 8*DM; i += blockDim.x) se[i] = emb[i];
    __syncthreads();
    int e = blockIdx.x*blockDim.x + threadIdx.x;
    if (e >= DIP) return;
    float acc[8] = {0.f,0.f,0.f,0.f,0.f,0.f,0.f,0.f};
    const float* wr = W + (size_t)e*DM;
    for (int d = 0; d < DM; d++) {
        float wv = wr[d];
        #pragma unroll
        for (int v = 0; v < 8; v++) acc[v] += wv * se[v*DM + d];
    }
    #pragma unroll
    for (int v = 0; v < 8; v++) g_lut[(size_t)v*DIP + e] = acc[v];
}

__global__ void k_gather(const int* __restrict__ ids) {
    int bt = blockIdx.x;
    const float4* src = (const float4*)(g_lut + (size_t)ids[bt]*DIP);
    float4* dst = (float4*)(g_zx + (size_t)bt*DIP);
    for (int i = threadIdx.x; i < DIP/4; i += blockDim.x) dst[i] = src[i];
}

// ---------------- conv4 + silu + softplus(dt) + dA ----------------
__global__ void k_conv(const float* __restrict__ cw, const float* __restrict__ cb,
                       const float* __restrict__ dtb, const float* __restrict__ Alog) {
    int bt = blockIdx.x;
    int t  = bt & (SEQ-1);
    for (int c = threadIdx.x; c < CDIM; c += blockDim.x) {
        float acc = cb[c];
        #pragma unroll
        for (int k = 0; k < 4; k++) {
            int tt = t - 3 + k;
            if (tt >= 0) acc += g_zx[(size_t)(bt - 3 + k)*DIP + DI + c] * cw[c*4 + k];
        }
        g_xbc[(size_t)bt*CDIM + c] = siluf(acc);
    }
    if (threadIdx.x < NH) {
        int h = threadIdx.x;
        float xr  = g_zx[(size_t)bt*DIP + DI + CDIM + h] + dtb[h];
        float dtv = (xr > 20.f) ? xr : log1pf(expf(xr));
        g_dt[bt*NH + h] = dtv;
        g_dA[bt*NH + h] = expf(dtv * (-expf(Alog[h])));
    }
}

// ---------------- SSD scan ----------------
__global__ void k_scan(const float* __restrict__ Dp) {
    int h = blockIdx.x, b = blockIdx.y;
    int tid = threadIdx.x;
    int p = tid >> 2, q = tid & 3;
    float Dh = Dp[h];
    float hreg[16];
    #pragma unroll
    for (int i = 0; i < 16; i++) hreg[i] = 0.f;

    __shared__ float sx[16][64], sB[16][64], sC[16][64];
    __shared__ float sdt[16], sdA[16];

    for (int t0 = 0; t0 < SEQ; t0 += 16) {
        for (int i = tid; i < 16*64; i += 256) {
            int s = i >> 6, j = i & 63;
            const float* row = g_xbc + (size_t)(b*SEQ + t0 + s)*CDIM;
            sx[s][j] = row[h*HD + j];
            sB[s][j] = row[DI + j];
            sC[s][j] = row[DI + NS + j];
        }
        if (tid < 16) {
            sdt[tid] = g_dt[(b*SEQ + t0 + tid)*NH + h];
            sdA[tid] = g_dA[(b*SEQ + t0 + tid)*NH + h];
        }
        __syncthreads();
        #pragma unroll 4
        for (int s = 0; s < 16; s++) {
            float da  = sdA[s];
            float xv  = sx[s][p];
            float dtx = sdt[s] * xv;
            float y = 0.f;
            #pragma unroll
            for (int i = 0; i < 16; i++) {
                int n = q + 4*i;
                hreg[i] = hreg[i]*da + dtx*sB[s][n];
                y += hreg[i]*sC[s][n];
            }
            y += __shfl_xor_sync(0xffffffffu, y, 1);
            y += __shfl_xor_sync(0xffffffffu, y, 2);
            if (q == 0)
                g_ys[(size_t)(b*SEQ + t0 + s)*DI + h*HD + p] = y + xv*Dh;
        }
        __syncthreads();
    }
}

// ---------------- gate + RMSNorm -> writes split-bf16 triple g_a3 ----------------
__global__ void k_gate(const float* __restrict__ nw) {
    int bt = blockIdx.x, tid = threadIdx.x;
    const float* ysr = g_ys + (size_t)bt*DI;
    const float* zr  = g_zx + (size_t)bt*DIP;
    float v0 = ysr[tid]       * siluf(zr[tid]);
    float v1 = ysr[tid + 256] * siluf(zr[tid + 256]);
    __shared__ float red[256];
    red[tid] = v0*v0 + v1*v1;
    __syncthreads();
    for (int s = 128; s > 0; s >>= 1) {
        if (tid < s) red[tid] += red[tid + s];
        __syncthreads();
    }
    float scale = rsqrtf(red[0] * (1.f/DI) + 1e-5f);
    float y0 = v0*scale*nw[tid];
    float y1 = v1*scale*nw[tid + 256];
    __nv_bfloat16* a3 = g_a3 + (size_t)bt*(3*DI);
    __nv_bfloat16 h0 = __float2bfloat16_rn(y0);
    __nv_bfloat16 l0 = __float2bfloat16_rn(y0 - __bfloat162float(h0));
    __nv_bfloat16 h1 = __float2bfloat16_rn(y1);
    __nv_bfloat16 l1 = __float2bfloat16_rn(y1 - __bfloat162float(h1));
    a3[tid] = h0;  a3[DI + tid] = h0;  a3[2*DI + tid] = l0;
    a3[tid+256] = h1; a3[DI + tid+256] = h1; a3[2*DI + tid+256] = l1;
}

// ---------------- weight triple conversion: W3 = [Wh | Wl | Wh] ----------------
__global__ void k_cvtW(const float* __restrict__ W, __nv_bfloat16* __restrict__ W3,
                       int N, int Npad, int K) {
    int idx = blockIdx.x*blockDim.x + threadIdx.x;
    if (idx >= Npad*K) return;
    int n = idx / K, k = idx % K;
    float w = (n < N) ? W[(size_t)n*K + k] : 0.f;
    __nv_bfloat16 h = __float2bfloat16_rn(w);
    __nv_bfloat16 l = __float2bfloat16_rn(w - __bfloat162float(h));
    __nv_bfloat16* row = W3 + (size_t)n*(3*K);
    row[k] = h; row[K + k] = l; row[2*K + k] = h;
}

// ---------------- tensor-core GEMM: C[m,n] = A[m,:Kp] . W[n,:Kp] (+R), fp32 acc ----------------
// Block tile 128x64, BK=32, 256 threads (8 warps, 4m x 2n, 32x32 per warp).
#define GBM 128
#define GBN 64
#define GBK 32

template<bool RESID, bool W3OUT>
__global__ void __launch_bounds__(256) k_mma(
        const __nv_bfloat16* __restrict__ A,   // [M][Kp]
        const __nv_bfloat16* __restrict__ W,   // [Npad][Kp]
        const float* __restrict__ R,
        float* __restrict__ C,                 // [M][ldc]
        __nv_bfloat16* __restrict__ X3,        // triple out [M][3*N] (W3OUT)
        int N, int Kp, int ldc)
{
    __shared__ __nv_bfloat16 As[GBM][GBK+8];
    __shared__ __nv_bfloat16 Ws[GBN][GBK+8];
    int tid = threadIdx.x;
    int warp = tid >> 5, lane = tid & 31;
    int wm = warp & 3, wn = warp >> 2;
    int m0 = blockIdx.y * GBM;
    int n0 = blockIdx.x * GBN;

    float acc[2][4][4];
    #pragma unroll
    for (int i = 0; i < 2; i++)
        #pragma unroll
        for (int j = 0; j < 4; j++)
            #pragma unroll
            for (int e = 0; e < 4; e++) acc[i][j][e] = 0.f;

    for (int k0 = 0; k0 < Kp; k0 += GBK) {
        #pragma unroll
        for (int i = 0; i < 2; i++) {
            int c = tid + i*256;
            int r = c >> 2, kc = (c & 3) * 8;
            *(float4*)&As[r][kc] = *(const float4*)&A[(size_t)(m0 + r)*Kp + k0 + kc];
        }
        {
            int r = tid >> 2, kc = (tid & 3) * 8;
            *(float4*)&Ws[r][kc] = *(const float4*)&W[(size_t)(n0 + r)*Kp + k0 + kc];
        }
        __syncthreads();
        #pragma unroll
        for (int kk = 0; kk < GBK; kk += 16) {
            unsigned int af[2][4];
            #pragma unroll
            for (int i = 0; i < 2; i++) {
                int row = wm*32 + i*16 + (lane & 15);
                int col = kk + ((lane >> 4) << 3);
                unsigned int addr = (unsigned int)__cvta_generic_to_shared(&As[row][col]);
                asm volatile("ldmatrix.sync.aligned.m8n8.x4.shared.b16 {%0,%1,%2,%3}, [%4];\n"
                    : "=r"(af[i][0]), "=r"(af[i][1]), "=r"(af[i][2]), "=r"(af[i][3]) : "r"(addr));
            }
            unsigned int bfm[2][4];
            #pragma unroll
            for (int g = 0; g < 2; g++) {
                int row = wn*32 + g*16 + (lane & 15);
                int col = kk + ((lane >> 4) << 3);
                unsigned int addr = (unsigned int)__cvta_generic_to_shared(&Ws[row][col]);
                asm volatile("ldmatrix.sync.aligned.m8n8.x4.shared.b16 {%0,%1,%2,%3}, [%4];\n"
                    : "=r"(bfm[g][0]), "=r"(bfm[g][1]), "=r"(bfm[g][2]), "=r"(bfm[g][3]) : "r"(addr));
            }
            #pragma unroll
            for (int i = 0; i < 2; i++) {
                #pragma unroll
                for (int g = 0; g < 2; g++) {
                    #pragma unroll
                    for (int s = 0; s < 2; s++) {
                        int j = g*2 + s;
                        asm volatile(
                            "mma.sync.aligned.m16n8k16.row.col.f32.bf16.bf16.f32 "
                            "{%0,%1,%2,%3}, {%4,%5,%6,%7}, {%8,%9}, {%0,%1,%2,%3};\n"
                            : "+f"(acc[i][j][0]), "+f"(acc[i][j][1]),
                              "+f"(acc[i][j][2]), "+f"(acc[i][j][3])
                            : "r"(af[i][0]), "r"(af[i][1]), "r"(af[i][2]), "r"(af[i][3]),
                              "r"(bfm[g][s]), "r"(bfm[g][s+2]));
                    }
                }
            }
        }
        __syncthreads();
    }

    // epilogue
    #pragma unroll
    for (int i = 0; i < 2; i++) {
        #pragma unroll
        for (int j = 0; j < 4; j++) {
            int ncol = n0 + wn*32 + (j>>1)*16 + (j&1)*8 + (lane & 3)*2;
            #pragma unroll
            for (int half = 0; half < 2; half++) {
                int m = m0 + wm*32 + i*16 + (lane >> 2) + half*8;
                #pragma unroll
                for (int e = 0; e < 2; e++) {
                    int n = ncol + e;
                    if (n < N) {
                        float v = acc[i][j][half*2 + e];
                        if (RESID) v += R[(size_t)m*ldc + n];
                        C[(size_t)m*ldc + n] = v;
                        if (W3OUT) {
                            __nv_bfloat16 h = __float2bfloat16_rn(v);
                            __nv_bfloat16 l = __float2bfloat16_rn(v - __bfloat162float(h));
                            __nv_bfloat16* row = X3 + (size_t)m*(3*N);
                            row[n] = h; row[N + n] = h; row[2*N + n] = l;
                        }
                    }
                }
            }
        }
    }
}

// ---------------- pooling ----------------
__global__ void k_pool1() {
    int seg = blockIdx.x, b = blockIdx.y, d = threadIdx.x;
    float sum = 0.f, mx = -INFINITY;
    for (int i = 0; i < 64; i++) {
        float v = g_x[(size_t)(b*SEQ + seg*64 + i)*DM + d];
        sum += v; mx = fmaxf(mx, v);
    }
    g_psum[(b*16 + seg)*DM + d] = sum;
    g_pmax[(b*16 + seg)*DM + d] = mx;
}
__global__ void k_pool2() {
    int b = blockIdx.x, d = threadIdx.x;
    float sum = 0.f, mx = -INFINITY;
    for (int s = 0; s < 16; s++) {
        sum += g_psum[(b*16 + s)*DM + d];
        mx = fmaxf(mx, g_pmax[(b*16 + s)*DM + d]);
    }
    g_pooled[b*DM + d] = (sum*(1.f/SEQ) + mx)*0.5f;
}

// ---------------- classification head ----------------
__global__ void k_head(const float* __restrict__ pw, const float* __restrict__ pb,
                       const float* __restrict__ c1w, const float* __restrict__ c1b,
                       const float* __restrict__ c2w, const float* __restrict__ c2b,
                       float* __restrict__ out) {
    int b = blockIdx.x, tid = threadIdx.x;
    __shared__ float sp[DM], s1[DM], s2[128];
    sp[tid] = g_pooled[b*DM + tid];
    __syncthreads();
    {
        float acc = pb[tid];
        const float* wr = pw + (size_t)tid*DM;
        for (int d = 0; d < DM; d++) acc += sp[d]*wr[d];
        s1[tid] = geluf(acc);
    }
    __syncthreads();
    if (tid < 128) {
        float acc = c1b[tid];
        const float* wr = c1w + (size_t)tid*DM;
        for (int d = 0; d < DM; d++) acc += s1[d]*wr[d];
        s2[tid] = geluf(acc);
    }
    __syncthreads();
    if (tid < 2) {
        float acc = c2b[tid];
        const float* wr = c2w + tid*128;
        for (int d = 0; d < 128; d++) acc += s2[d]*wr[d];
        out[b*2 + tid] = acc;
    }
}

// ---------------- launch ----------------
extern "C" void kernel_launch(void* const* d_in, const int* in_sizes, int n_in,
                              void* d_out, int out_size) {
    const int*   ids  = (const int*)  d_in[0];
    const float* emb  = (const float*)d_in[1];
    const float* inw  = (const float*)d_in[2];
    const float* cw   = (const float*)d_in[3];
    const float* cb   = (const float*)d_in[4];
    const float* dtb  = (const float*)d_in[5];
    const float* alog = (const float*)d_in[6];
    const float* Dv   = (const float*)d_in[7];
    const float* nw   = (const float*)d_in[8];
    const float* ow   = (const float*)d_in[9];
    const float* pw   = (const float*)d_in[10];
    const float* pb   = (const float*)d_in[11];
    const float* c1w  = (const float*)d_in[12];
    const float* c1b  = (const float*)d_in[13];
    const float* c2w  = (const float*)d_in[14];
    const float* c2b  = (const float*)d_in[15];
    float* out = (float*)d_out;

    float *px, *pzx;
    __nv_bfloat16 *pa3, *px3, *pw3a, *pw3b;
    cudaGetSymbolAddress((void**)&px,   g_x);
    cudaGetSymbolAddress((void**)&pzx,  g_zx);
    cudaGetSymbolAddress((void**)&pa3,  g_a3);
    cudaGetSymbolAddress((void**)&px3,  g_x3);
    cudaGetSymbolAddress((void**)&pw3a, g_w3a);
    cudaGetSymbolAddress((void**)&pw3b, g_w3b);

    k_embed<<<NTOK, DM>>>(ids, emb);

    // ---- layer 0 ----
    k_lut<<<(DIP + 255)/256, 256>>>(emb, inw);
    k_gather<<<NTOK, 256>>>(ids);
    k_conv<<<NTOK, 256>>>(cw, cb, dtb, alog);
    k_scan<<<dim3(NH, BATCH), 256>>>(Dv);
    k_gate<<<NTOK, 256>>>(nw);
    k_cvtW<<<(DM*DI + 255)/256, 256>>>(ow, pw3b, DM, DM, DI);
    // out_proj: M=8192, N=256, Kp=1536; residual add; emit x3 triple for layer-1 in_proj
    k_mma<true, true><<<dim3(DM/GBN, NTOK/GBM), 256>>>(
        pa3, pw3b, px, px, px3, DM, 3*DI, DM);

    // ---- layer 1 ----
    k_cvtW<<<(NPAD_IN*DM + 255)/256, 256>>>(inw + (size_t)DIP*DM, pw3a, DIP, NPAD_IN, DM);
    // in_proj: M=8192, N=1160 (pad 1216), Kp=768
    k_mma<false, false><<<dim3(NPAD_IN/GBN, NTOK/GBM), 256>>>(
        px3, pw3a, nullptr, pzx, nullptr, DIP, 3*DM, DIP);
    k_conv<<<NTOK, 256>>>(cw + (size_t)CDIM*4, cb + CDIM, dtb + NH, alog + NH);
    k_scan<<<dim3(NH, BATCH), 256>>>(Dv + NH);
    k_gate<<<NTOK, 256>>>(nw + DI);
    k_cvtW<<<(DM*DI + 255)/256, 256>>>(ow + (size_t)DM*DI, pw3b, DM, DM, DI);
    k_mma<true, false><<<dim3(DM/GBN, NTOK/GBM), 256>>>(
        pa3, pw3b, px, px, nullptr, DM, 3*DI, DM);

    k_pool1<<<dim3(16, BATCH), DM>>>();
    k_pool2<<<BATCH, DM>>>();
    k_head<<<BATCH, DM>>>(pw, pb, c1w, c1b, c2w, c2b, out);
}

// round 4
// speedup vs baseline: 1.2719x; 1.1523x over previous
#include <cuda_runtime.h>
#include <cuda_bf16.h>
#include <cstdint>
#include <math.h>

#define BATCH 8
#define SEQ   1024
#define DM    256
#define DI    512
#define NH    8
#define HD    64
#define NS    64
#define CDIM  640
#define DIP   1160
#define NTOK  (BATCH*SEQ)   // 8192
#define NPAD_IN 1280        // 10*128

// ---------------- device scratch ----------------
__device__ float g_x[NTOK*DM];
__device__ float g_zx[NTOK*DIP];
__device__ float g_xbc[NTOK*CDIM];
__device__ float g_dt[NTOK*NH];
__device__ float g_dA[NTOK*NH];
__device__ float g_yp[4*NTOK*DI];     // 4 partial scan outputs (state-split)
__device__ float g_lut[8*DIP];
__device__ float g_psum[BATCH*16*DM];
__device__ float g_pmax[BATCH*16*DM];
__device__ float g_pooled[BATCH*DM];
__device__ __align__(16) __nv_bfloat16 g_a3[NTOK*3*DI];
__device__ __align__(16) __nv_bfloat16 g_x3[NTOK*3*DM];
__device__ __align__(16) __nv_bfloat16 g_w3a[NPAD_IN*3*DM];
__device__ __align__(16) __nv_bfloat16 g_w3b[DM*3*DI];

__device__ __forceinline__ float siluf(float x) { return x / (1.f + expf(-x)); }
__device__ __forceinline__ float geluf(float x) { return 0.5f * x * (1.f + erff(x * 0.7071067811865476f)); }

template<int N> __device__ __forceinline__ void cp_wait() {
    asm volatile("cp.async.wait_group %0;\n" :: "n"(N));
}
__device__ __forceinline__ void cp_commit() {
    asm volatile("cp.async.commit_group;\n");
}

// ---------------- embedding gather ----------------
__global__ void k_embed(const int* __restrict__ ids, const float* __restrict__ emb) {
    int bt = blockIdx.x;
    int d  = threadIdx.x;
    g_x[(size_t)bt*DM + d] = emb[(size_t)ids[bt]*DM + d];
}

// ---------------- layer-0 in_proj LUT ----------------
__global__ void k_lut(const float* __restrict__ emb, const float* __restrict__ W) {
    __shared__ float se[8*DM];
    for (int i = threadIdx.x; i < 8*DM; i += blockDim.x) se[i] = emb[i];
    __syncthreads();
    int e = blockIdx.x*blockDim.x + threadIdx.x;
    if (e >= DIP) return;
    float acc[8] = {0.f,0.f,0.f,0.f,0.f,0.f,0.f,0.f};
    const float* wr = W + (size_t)e*DM;
    for (int d = 0; d < DM; d++) {
        float wv = wr[d];
        #pragma unroll
        for (int v = 0; v < 8; v++) acc[v] += wv * se[v*DM + d];
    }
    #pragma unroll
    for (int v = 0; v < 8; v++) g_lut[(size_t)v*DIP + e] = acc[v];
}

__global__ void k_gather(const int* __restrict__ ids) {
    int bt = blockIdx.x;
    const float4* src = (const float4*)(g_lut + (size_t)ids[bt]*DIP);
    float4* dst = (float4*)(g_zx + (size_t)bt*DIP);
    for (int i = threadIdx.x; i < DIP/4; i += blockDim.x) dst[i] = src[i];
}

// ---------------- conv4 + silu + softplus(dt) + dA ----------------
__global__ void k_conv(const float* __restrict__ cw, const float* __restrict__ cb,
                       const float* __restrict__ dtb, const float* __restrict__ Alog) {
    int bt = blockIdx.x;
    int t  = bt & (SEQ-1);
    for (int c = threadIdx.x; c < CDIM; c += blockDim.x) {
        float acc = cb[c];
        #pragma unroll
        for (int k = 0; k < 4; k++) {
            int tt = t - 3 + k;
            if (tt >= 0) acc += g_zx[(size_t)(bt - 3 + k)*DIP + DI + c] * cw[c*4 + k];
        }
        g_xbc[(size_t)bt*CDIM + c] = siluf(acc);
    }
    if (threadIdx.x < NH) {
        int h = threadIdx.x;
        float xr  = g_zx[(size_t)bt*DIP + DI + CDIM + h] + dtb[h];
        float dtv = (xr > 20.f) ? xr : log1pf(expf(xr));
        g_dt[bt*NH + h] = dtv;
        g_dA[bt*NH + h] = expf(dtv * (-expf(Alog[h])));
    }
}

// ---------------- SSD scan, 4-way state split: grid (NH, BATCH, 4) ----------------
__global__ void k_scan(float* __restrict__ yp) {
    int h = blockIdx.x, b = blockIdx.y, ng = blockIdx.z;
    int tid = threadIdx.x;
    int p = tid >> 2, q = tid & 3;
    float hreg[4] = {0.f, 0.f, 0.f, 0.f};

    __shared__ float sx[16][64], sB[16][16], sC[16][16];
    __shared__ float sdt[16], sdA[16];

    float* ypg = yp + (size_t)ng*NTOK*DI;

    for (int t0 = 0; t0 < SEQ; t0 += 16) {
        for (int i = tid; i < 16*64; i += 256) {
            int s = i >> 6, j = i & 63;
            sx[s][j] = g_xbc[(size_t)(b*SEQ + t0 + s)*CDIM + h*HD + j];
        }
        for (int i = tid; i < 16*16; i += 256) {
            int s = i >> 4, j = i & 15;
            const float* row = g_xbc + (size_t)(b*SEQ + t0 + s)*CDIM;
            sB[s][j] = row[DI + ng*16 + j];
            sC[s][j] = row[DI + NS + ng*16 + j];
        }
        if (tid < 16) {
            sdt[tid] = g_dt[(b*SEQ + t0 + tid)*NH + h];
            sdA[tid] = g_dA[(b*SEQ + t0 + tid)*NH + h];
        }
        __syncthreads();
        #pragma unroll 4
        for (int s = 0; s < 16; s++) {
            float da  = sdA[s];
            float xv  = sx[s][p];
            float dtx = sdt[s] * xv;
            float y = 0.f;
            #pragma unroll
            for (int i = 0; i < 4; i++) {
                int n = q + 4*i;
                hreg[i] = hreg[i]*da + dtx*sB[s][n];
                y += hreg[i]*sC[s][n];
            }
            y += __shfl_xor_sync(0xffffffffu, y, 1);
            y += __shfl_xor_sync(0xffffffffu, y, 2);
            if (q == 0)
                ypg[(size_t)(b*SEQ + t0 + s)*DI + h*HD + p] = y;
        }
        __syncthreads();
    }
}

// ---------------- gate: sum partials + x*D, *silu(z), RMSNorm -> bf16 triple ----------------
__global__ void k_gate(const float* __restrict__ nw, const float* __restrict__ Dp) {
    int bt = blockIdx.x, tid = threadIdx.x;
    const float* zr  = g_zx  + (size_t)bt*DIP;
    const float* xbr = g_xbc + (size_t)bt*CDIM;
    size_t base = (size_t)bt*DI;
    float v[2];
    #pragma unroll
    for (int u = 0; u < 2; u++) {
        int d = tid + u*256;
        float ys = g_yp[base + d] + g_yp[(size_t)NTOK*DI + base + d]
                 + g_yp[2*(size_t)NTOK*DI + base + d] + g_yp[3*(size_t)NTOK*DI + base + d];
        ys += xbr[d] * Dp[d >> 6];
        v[u] = ys * siluf(zr[d]);
    }
    __shared__ float red[256];
    red[tid] = v[0]*v[0] + v[1]*v[1];
    __syncthreads();
    for (int s = 128; s > 0; s >>= 1) {
        if (tid < s) red[tid] += red[tid + s];
        __syncthreads();
    }
    float scale = rsqrtf(red[0] * (1.f/DI) + 1e-5f);
    __nv_bfloat16* a3 = g_a3 + (size_t)bt*(3*DI);
    #pragma unroll
    for (int u = 0; u < 2; u++) {
        int d = tid + u*256;
        float y = v[u]*scale*nw[d];
        __nv_bfloat16 hh = __float2bfloat16_rn(y);
        __nv_bfloat16 ll = __float2bfloat16_rn(y - __bfloat162float(hh));
        a3[d] = hh;  a3[DI + d] = hh;  a3[2*DI + d] = ll;
    }
}

// ---------------- weight triple conversion: W3 = [Wh | Wl | Wh] ----------------
__global__ void k_cvtW(const float* __restrict__ W, __nv_bfloat16* __restrict__ W3,
                       int N, int Npad, int K) {
    int idx = blockIdx.x*blockDim.x + threadIdx.x;
    if (idx >= Npad*K) return;
    int n = idx / K, k = idx % K;
    float w = (n < N) ? W[(size_t)n*K + k] : 0.f;
    __nv_bfloat16 h = __float2bfloat16_rn(w);
    __nv_bfloat16 l = __float2bfloat16_rn(w - __bfloat162float(h));
    __nv_bfloat16* row = W3 + (size_t)n*(3*K);
    row[k] = h; row[K + k] = l; row[2*K + k] = h;
}

// ---------------- pipelined tensor-core GEMM: 128x128 tile, BK=32, cp.async x2 ----------------
#define GBM 128
#define GBN 128
#define GBK 32

template<bool RESID, bool W3OUT>
__global__ void __launch_bounds__(256) k_mma(
        const __nv_bfloat16* __restrict__ A,   // [M][Kp]
        const __nv_bfloat16* __restrict__ W,   // [Npad][Kp]
        const float* __restrict__ R,
        float* __restrict__ C,                 // [M][ldc]
        __nv_bfloat16* __restrict__ X3,        // triple out [M][3*N] (W3OUT)
        int N, int Kp, int ldc)
{
    __shared__ __nv_bfloat16 As[2][GBM][GBK+8];
    __shared__ __nv_bfloat16 Ws[2][GBN][GBK+8];
    int tid = threadIdx.x;
    int warp = tid >> 5, lane = tid & 31;
    int wm = warp >> 2, wn = warp & 3;   // 2m x 4n; warp tile 64x32
    int m0 = blockIdx.y * GBM;
    int n0 = blockIdx.x * GBN;

    float acc[4][4][4];
    #pragma unroll
    for (int i = 0; i < 4; i++)
        #pragma unroll
        for (int j = 0; j < 4; j++)
            #pragma unroll
            for (int e = 0; e < 4; e++) acc[i][j][e] = 0.f;

    int nk = Kp / GBK;

    // stage loader: 512 16B chunks for A, 512 for W; 256 threads -> 2+2 each
    auto load_stage = [&](int st, int k0) {
        #pragma unroll
        for (int u = 0; u < 2; u++) {
            int idx = tid + u*256;
            int r = idx >> 2, c = (idx & 3)*8;
            unsigned int da = (unsigned int)__cvta_generic_to_shared(&As[st][r][c]);
            asm volatile("cp.async.cg.shared.global [%0], [%1], 16;\n"
                :: "r"(da), "l"(A + (size_t)(m0 + r)*Kp + k0 + c));
            unsigned int dw = (unsigned int)__cvta_generic_to_shared(&Ws[st][r][c]);
            asm volatile("cp.async.cg.shared.global [%0], [%1], 16;\n"
                :: "r"(dw), "l"(W + (size_t)(n0 + r)*Kp + k0 + c));
        }
    };

    load_stage(0, 0);
    cp_commit();

    for (int it = 0; it < nk; it++) {
        int st = it & 1;
        if (it + 1 < nk) {
            load_stage(st ^ 1, (it + 1)*GBK);
            cp_commit();
            cp_wait<1>();
        } else {
            cp_wait<0>();
        }
        __syncthreads();

        #pragma unroll
        for (int kk = 0; kk < GBK; kk += 16) {
            unsigned int af[4][4];
            #pragma unroll
            for (int i = 0; i < 4; i++) {
                int row = wm*64 + i*16 + (lane & 15);
                int col = kk + ((lane >> 4) << 3);
                unsigned int addr = (unsigned int)__cvta_generic_to_shared(&As[st][row][col]);
                asm volatile("ldmatrix.sync.aligned.m8n8.x4.shared.b16 {%0,%1,%2,%3}, [%4];\n"
                    : "=r"(af[i][0]), "=r"(af[i][1]), "=r"(af[i][2]), "=r"(af[i][3]) : "r"(addr));
            }
            unsigned int bfm[2][4];
            #pragma unroll
            for (int g = 0; g < 2; g++) {
                int row = wn*32 + g*16 + (lane & 15);
                int col = kk + ((lane >> 4) << 3);
                unsigned int addr = (unsigned int)__cvta_generic_to_shared(&Ws[st][row][col]);
                asm volatile("ldmatrix.sync.aligned.m8n8.x4.shared.b16 {%0,%1,%2,%3}, [%4];\n"
                    : "=r"(bfm[g][0]), "=r"(bfm[g][1]), "=r"(bfm[g][2]), "=r"(bfm[g][3]) : "r"(addr));
            }
            #pragma unroll
            for (int i = 0; i < 4; i++) {
                #pragma unroll
                for (int g = 0; g < 2; g++) {
                    #pragma unroll
                    for (int s = 0; s < 2; s++) {
                        int j = g*2 + s;
                        asm volatile(
                            "mma.sync.aligned.m16n8k16.row.col.f32.bf16.bf16.f32 "
                            "{%0,%1,%2,%3}, {%4,%5,%6,%7}, {%8,%9}, {%0,%1,%2,%3};\n"
                            : "+f"(acc[i][j][0]), "+f"(acc[i][j][1]),
                              "+f"(acc[i][j][2]), "+f"(acc[i][j][3])
                            : "r"(af[i][0]), "r"(af[i][1]), "r"(af[i][2]), "r"(af[i][3]),
                              "r"(bfm[g][s]), "r"(bfm[g][s+2]));
                    }
                }
            }
        }
        __syncthreads();
    }

    // epilogue
    #pragma unroll
    for (int i = 0; i < 4; i++) {
        #pragma unroll
        for (int j = 0; j < 4; j++) {
            int ncol = n0 + wn*32 + j*8 + (lane & 3)*2;
            #pragma unroll
            for (int half = 0; half < 2; half++) {
                int m = m0 + wm*64 + i*16 + (lane >> 2) + half*8;
                #pragma unroll
                for (int e = 0; e < 2; e++) {
                    int n = ncol + e;
                    if (n < N) {
                        float v = acc[i][j][half*2 + e];
                        if (RESID) v += R[(size_t)m*ldc + n];
                        C[(size_t)m*ldc + n] = v;
                        if (W3OUT) {
                            __nv_bfloat16 h = __float2bfloat16_rn(v);
                            __nv_bfloat16 l = __float2bfloat16_rn(v - __bfloat162float(h));
                            __nv_bfloat16* row = X3 + (size_t)m*(3*N);
                            row[n] = h; row[N + n] = h; row[2*N + n] = l;
                        }
                    }
                }
            }
        }
    }
}

// ---------------- pooling ----------------
__global__ void k_pool1() {
    int seg = blockIdx.x, b = blockIdx.y, d = threadIdx.x;
    float sum = 0.f, mx = -INFINITY;
    for (int i = 0; i < 64; i++) {
        float v = g_x[(size_t)(b*SEQ + seg*64 + i)*DM + d];
        sum += v; mx = fmaxf(mx, v);
    }
    g_psum[(b*16 + seg)*DM + d] = sum;
    g_pmax[(b*16 + seg)*DM + d] = mx;
}
__global__ void k_pool2() {
    int b = blockIdx.x, d = threadIdx.x;
    float sum = 0.f, mx = -INFINITY;
    for (int s = 0; s < 16; s++) {
        sum += g_psum[(b*16 + s)*DM + d];
        mx = fmaxf(mx, g_pmax[(b*16 + s)*DM + d]);
    }
    g_pooled[b*DM + d] = (sum*(1.f/SEQ) + mx)*0.5f;
}

// ---------------- classification head ----------------
__global__ void k_head(const float* __restrict__ pw, const float* __restrict__ pb,
                       const float* __restrict__ c1w, const float* __restrict__ c1b,
                       const float* __restrict__ c2w, const float* __restrict__ c2b,
                       float* __restrict__ out) {
    int b = blockIdx.x, tid = threadIdx.x;
    __shared__ float sp[DM], s1[DM], s2[128];
    sp[tid] = g_pooled[b*DM + tid];
    __syncthreads();
    {
        float acc = pb[tid];
        const float* wr = pw + (size_t)tid*DM;
        for (int d = 0; d < DM; d++) acc += sp[d]*wr[d];
        s1[tid] = geluf(acc);
    }
    __syncthreads();
    if (tid < 128) {
        float acc = c1b[tid];
        const float* wr = c1w + (size_t)tid*DM;
        for (int d = 0; d < DM; d++) acc += s1[d]*wr[d];
        s2[tid] = geluf(acc);
    }
    __syncthreads();
    if (tid < 2) {
        float acc = c2b[tid];
        const float* wr = c2w + tid*128;
        for (int d = 0; d < 128; d++) acc += s2[d]*wr[d];
        out[b*2 + tid] = acc;
    }
}

// ---------------- launch ----------------
extern "C" void kernel_launch(void* const* d_in, const int* in_sizes, int n_in,
                              void* d_out, int out_size) {
    const int*   ids  = (const int*)  d_in[0];
    const float* emb  = (const float*)d_in[1];
    const float* inw  = (const float*)d_in[2];
    const float* cw   = (const float*)d_in[3];
    const float* cb   = (const float*)d_in[4];
    const float* dtb  = (const float*)d_in[5];
    const float* alog = (const float*)d_in[6];
    const float* Dv   = (const float*)d_in[7];
    const float* nw   = (const float*)d_in[8];
    const float* ow   = (const float*)d_in[9];
    const float* pw   = (const float*)d_in[10];
    const float* pb   = (const float*)d_in[11];
    const float* c1w  = (const float*)d_in[12];
    const float* c1b  = (const float*)d_in[13];
    const float* c2w  = (const float*)d_in[14];
    const float* c2b  = (const float*)d_in[15];
    float* out = (float*)d_out;

    float *px, *pzx, *pyp;
    __nv_bfloat16 *pa3, *px3, *pw3a, *pw3b;
    cudaGetSymbolAddress((void**)&px,   g_x);
    cudaGetSymbolAddress((void**)&pzx,  g_zx);
    cudaGetSymbolAddress((void**)&pyp,  g_yp);
    cudaGetSymbolAddress((void**)&pa3,  g_a3);
    cudaGetSymbolAddress((void**)&px3,  g_x3);
    cudaGetSymbolAddress((void**)&pw3a, g_w3a);
    cudaGetSymbolAddress((void**)&pw3b, g_w3b);

    k_embed<<<NTOK, DM>>>(ids, emb);

    // ---- layer 0 ----
    k_lut<<<(DIP + 255)/256, 256>>>(emb, inw);
    k_gather<<<NTOK, 256>>>(ids);
    k_conv<<<NTOK, 256>>>(cw, cb, dtb, alog);
    k_scan<<<dim3(NH, BATCH, 4), 256>>>(pyp);
    k_gate<<<NTOK, 256>>>(nw, Dv);
    k_cvtW<<<(DM*DI + 255)/256, 256>>>(ow, pw3b, DM, DM, DI);
    k_mma<true, true><<<dim3(DM/GBN, NTOK/GBM), 256>>>(
        pa3, pw3b, px, px, px3, DM, 3*DI, DM);

    // ---- layer 1 ----
    k_cvtW<<<(NPAD_IN*DM + 255)/256, 256>>>(inw + (size_t)DIP*DM, pw3a, DIP, NPAD_IN, DM);
    k_mma<false, false><<<dim3(NPAD_IN/GBN, NTOK/GBM), 256>>>(
        px3, pw3a, nullptr, pzx, nullptr, DIP, 3*DM, DIP);
    k_conv<<<NTOK, 256>>>(cw + (size_t)CDIM*4, cb + CDIM, dtb + NH, alog + NH);
    k_scan<<<dim3(NH, BATCH, 4), 256>>>(pyp);
    k_gate<<<NTOK, 256>>>(nw + DI, Dv + NH);
    k_cvtW<<<(DM*DI + 255)/256, 256>>>(ow + (size_t)DM*DI, pw3b, DM, DM, DI);
    k_mma<true, false><<<dim3(DM/GBN, NTOK/GBM), 256>>>(
        pa3, pw3b, px, px, nullptr, DM, 3*DI, DM);

    k_pool1<<<dim3(16, BATCH), DM>>>();
    k_pool2<<<BATCH, DM>>>();
    k_head<<<BATCH, DM>>>(pw, pb, c1w, c1b, c2w, c2b, out);
}